// round 15
// baseline (speedup 1.0000x reference)
#include <cuda_runtime.h>
#include <cstdint>

// out[n] = embedding[hash(trunc(x[n]*128))]  (reference's xf==0 collapses the
// trilerp to corner 0, weight 1; bit-exact).
// hash = (u0 ^ u1*2654435761 ^ u2*805459861) & (2^19 - 1)
//
// R15 (lock-in): kernel measured AT the HW floor. Six gather mechanisms
// (LDG.128/LDG.32/cp.async/TMA-bulk x2/nc+ca) all cap at ~0.36 random rows/
// cyc/SM => per-SM outstanding-sector pool ~87 @ ~248cyc L2 latency;
// 14.2K rows/SM / 0.36 ~= 40K cyc ~= 21.5us = measured. Shape: 8 lanes
// cooperatively gather one 32B row (1 sector/row), 4 rows per LDG.32;
// evict_last policy on table, streaming x/out. Micro-trims vs R14:
// 4 iterations/warp (128 pts), grid 2048 — fewer per-block fixed costs.

static constexpr unsigned P1 = 2654435761u;
static constexpr unsigned P2 = 805459861u;
static constexpr unsigned HASH_MASK = 524288u - 1u;  // 2^19
static constexpr int THREADS = 256;
static constexpr int ITERS = 4;
static constexpr int PTS_PER_BLOCK = 8 * 32 * ITERS;  // 1024

__device__ __forceinline__ unsigned hash3f(float a, float b, float c)
{
    unsigned u0 = (unsigned)__float2int_rz(a * 128.0f);
    unsigned u1 = (unsigned)__float2int_rz(b * 128.0f);
    unsigned u2 = (unsigned)__float2int_rz(c * 128.0f);
    return (u0 ^ (u1 * P1) ^ (u2 * P2)) & HASH_MASK;
}

__device__ __forceinline__ float ld_table(const float* p, unsigned long long pol)
{
    float v;
    asm volatile("ld.global.nc.L2::cache_hint.b32 %0, [%1], %2;"
                 : "=f"(v) : "l"(p), "l"(pol));
    return v;
}

__device__ __forceinline__ float ld_stream(const float* p)
{
    float v;
    asm volatile("ld.global.cs.b32 %0, [%1];" : "=f"(v) : "l"(p));
    return v;
}

__device__ __forceinline__ void st_stream(float* p, float v)
{
    asm volatile("st.global.cs.b32 [%0], %1;" :: "l"(p), "f"(v) : "memory");
}

__global__ void __launch_bounds__(THREADS)
hashgrid_octet_final_kernel(const float* __restrict__ x,
                            const float* __restrict__ embw,  // word view [H][8]
                            float* __restrict__ outw)        // word view [N][8]
{
    const int tid  = threadIdx.x;
    const int w    = tid >> 5;
    const int L    = tid & 31;
    const int sub  = L >> 3;   // which of 4 rows this lane helps gather
    const int word = L & 7;    // which 4B word of the 32B row

    unsigned long long pol;
    asm volatile("createpolicy.fractional.L2::evict_last.b64 %0, 1.0;"
                 : "=l"(pol));

    const size_t wb = (size_t)blockIdx.x * PTS_PER_BLOCK
                    + (size_t)w * (32 * ITERS);

    // ---- hash one point per lane, ITERS iterations (128 pts per warp) ----
    unsigned h[ITERS];
#pragma unroll
    for (int it = 0; it < ITERS; it++) {
        size_t p = wb + it * 32 + L;
        float a = ld_stream(&x[3 * p + 0]);
        float b = ld_stream(&x[3 * p + 1]);
        float c = ld_stream(&x[3 * p + 2]);
        h[it] = hash3f(a, b, c);
    }

    // ---- gather: 8*ITERS independent LDG.32, 4 rows per instruction,
    //      table pinned in L2 via evict_last policy ----
    float v[8 * ITERS];
#pragma unroll
    for (int it = 0; it < ITERS; it++) {
#pragma unroll
        for (int s = 0; s < 8; s++) {
            unsigned hs = __shfl_sync(0xFFFFFFFFu, h[it], 4 * s + sub);
            v[it * 8 + s] = ld_table(&embw[(size_t)hs * 8 + word], pol);
        }
    }

    // ---- stores: each STG.32 writes 128B contiguous (4 pts), evict-first ----
#pragma unroll
    for (int it = 0; it < ITERS; it++) {
#pragma unroll
        for (int s = 0; s < 8; s++) {
            size_t p = wb + it * 32 + 4 * s + sub;
            st_stream(&outw[p * 8 + word], v[it * 8 + s]);
        }
    }
}

// ---------------- fallback (proven R3) for non-multiple sizes ----------------

__global__ void __launch_bounds__(THREADS)
hashgrid_gather_ilp4_kernel(const float* __restrict__ x,
                            const float4* __restrict__ emb,
                            float4* __restrict__ out,
                            int n)
{
    int tid  = threadIdx.x;
    int w    = tid >> 5;
    int lane = tid & 31;
    int qw   = lane >> 1;
    int half = lane & 1;
    int base = blockIdx.x * 512 + w * 64 + qw;

    float xv[4][3];
#pragma unroll
    for (int k = 0; k < 4; k++) {
        int p = base + 16 * k;
        if (p < n) {
            xv[k][0] = x[3 * p + 0];
            xv[k][1] = x[3 * p + 1];
            xv[k][2] = x[3 * p + 2];
        }
    }
    unsigned h[4];
#pragma unroll
    for (int k = 0; k < 4; k++)
        h[k] = hash3f(xv[k][0], xv[k][1], xv[k][2]);

    float4 v[4];
#pragma unroll
    for (int k = 0; k < 4; k++)
        if (base + 16 * k < n) v[k] = __ldg(&emb[2 * h[k] + half]);
#pragma unroll
    for (int k = 0; k < 4; k++) {
        int p = base + 16 * k;
        if (p < n) out[2 * p + half] = v[k];
    }
}

extern "C" void kernel_launch(void* const* d_in, const int* in_sizes, int n_in,
                              void* d_out, int out_size)
{
    const float* x   = (const float*)d_in[0];
    const float* emb = (const float*)d_in[1];
    float*       out = (float*)d_out;

    int n = in_sizes[0] / 3;  // N_POINTS

    if (n % PTS_PER_BLOCK == 0) {
        int blocks = n / PTS_PER_BLOCK;  // 2048
        hashgrid_octet_final_kernel<<<blocks, THREADS>>>(x, emb, out);
    } else {
        int blocks = (n + 511) / 512;
        hashgrid_gather_ilp4_kernel<<<blocks, THREADS>>>(
            x, (const float4*)emb, (float4*)out, n);
    }
}